// round 2
// baseline (speedup 1.0000x reference)
#include <cuda_runtime.h>

// Problem constants
#define S_TOTAL    37448       // sum of LAYER_SIZES
#define OUT_TOKENS 5704        // 8 + 64 + 512 + 1024 + 4096
#define BATCH      8
#define NROWS      196         // 4 val rows + 3*64 pos rows
#define RCHUNK     14          // 14 * 14 == 196

// Scratch (static device globals; no runtime allocation)
__device__ float g_Wt3[4 * 256 * 256];        // [kk][e][o]
__device__ float g_Wt4[8 * 256 * 256];
__device__ float g_proj3[4 * NROWS * 256];    // [kk][row][o]
__device__ float g_proj4[8 * NROWS * 256];

// ---------------------------------------------------------------------------
// Kernel A: transpose conv_w  W[o][e][kk] -> Wt[kk][e][o]  (write-coalesced)
// ---------------------------------------------------------------------------
template <int K>
__global__ void transpose_w_kernel(const float* __restrict__ W) {
    float* Wt = (K == 4) ? g_Wt3 : g_Wt4;
    int idx = blockIdx.x * blockDim.x + threadIdx.x;   // [0, K*65536)
    if (idx >= K * 65536) return;
    int kk = idx >> 16;
    int e  = (idx >> 8) & 255;
    int o  = idx & 255;
    Wt[idx] = W[(o * 256 + e) * K + kk];
}

// ---------------------------------------------------------------------------
// Kernel B: project embedding rows through each W_kk slice.
// proj[kk][r][o] = sum_e row_r[e] * Wt[kk][e][o]
// block = (rchunk, kk); 256 threads, thread = o; 14 rows per block.
// ---------------------------------------------------------------------------
template <int K>
__global__ void __launch_bounds__(256) project_tables_kernel(
    const float* __restrict__ val_emb,   // (4, 256)
    const float* __restrict__ pos_emb)   // (3, 64, 256) contiguous
{
    const float* Wt = (K == 4) ? g_Wt3 : g_Wt4;
    float*     proj = (K == 4) ? g_proj3 : g_proj4;

    int kk = blockIdx.y;
    int r0 = blockIdx.x * RCHUNK;
    int o  = threadIdx.x;

    __shared__ float srow[RCHUNK][256];
#pragma unroll
    for (int r = 0; r < RCHUNK; r++) {
        int rr = r0 + r;
        const float* src = (rr < 4) ? (val_emb + rr * 256)
                                    : (pos_emb + (rr - 4) * 256);
        srow[r][o] = src[o];
    }
    __syncthreads();

    float acc[RCHUNK];
#pragma unroll
    for (int r = 0; r < RCHUNK; r++) acc[r] = 0.0f;

    const float* wt = Wt + kk * 65536 + o;
#pragma unroll 4
    for (int e = 0; e < 256; e++) {
        float w = wt[e * 256];
#pragma unroll
        for (int r = 0; r < RCHUNK; r++) acc[r] += srow[r][e] * w;
    }

    float* dst = proj + (kk * NROWS + r0) * 256 + o;
#pragma unroll
    for (int r = 0; r < RCHUNK; r++) dst[r * 256] = acc[r];
}

// ---------------------------------------------------------------------------
// Kernel C: layers 0-2 (pure embedding sum), 584 tokens per batch row.
// thread = (token, o4): 64 threads (float4) per token.
// ---------------------------------------------------------------------------
__global__ void __launch_bounds__(256) embed_small_kernel(
    const int* __restrict__ value,
    const int* __restrict__ depth,
    const int* __restrict__ position,
    const float* __restrict__ v0, const float* __restrict__ v1, const float* __restrict__ v2,
    const float* __restrict__ p0, const float* __restrict__ p1, const float* __restrict__ p2,
    const float* __restrict__ d0, const float* __restrict__ d1, const float* __restrict__ d2,
    float* __restrict__ out)
{
    int idx = blockIdx.x * blockDim.x + threadIdx.x;
    int lane  = idx & 63;
    int token = idx >> 6;
    if (token >= BATCH * 584) return;
    int b = token / 584;
    int s = token % 584;

    const float *ve, *pe, *de;
    if (s < 8)       { ve = v0; pe = p0; de = d0; }
    else if (s < 72) { ve = v1; pe = p1; de = d1; }
    else             { ve = v2; pe = p2; de = d2; }

    int base = b * S_TOTAL + s;
    int v = value[base];
    int d = depth[base];
    const int* pp = position + base * 3;
    int q0 = pp[0], q1 = pp[1], q2 = pp[2];

    const float4* V  = reinterpret_cast<const float4*>(ve) + v * 64 + lane;
    const float4* P0 = reinterpret_cast<const float4*>(pe) + (q0)      * 64 + lane;
    const float4* P1 = reinterpret_cast<const float4*>(pe) + (64 + q1) * 64 + lane;
    const float4* P2 = reinterpret_cast<const float4*>(pe) + (128 + q2)* 64 + lane;
    const float4* D  = reinterpret_cast<const float4*>(de) + d * 64 + lane;

    float4 a = *V, x;
    x = *P0; a.x += x.x; a.y += x.y; a.z += x.z; a.w += x.w;
    x = *P1; a.x += x.x; a.y += x.y; a.z += x.z; a.w += x.w;
    x = *P2; a.x += x.x; a.y += x.y; a.z += x.z; a.w += x.w;
    x = *D;  a.x += x.x; a.y += x.y; a.z += x.z; a.w += x.w;

    reinterpret_cast<float4*>(out)[(b * OUT_TOKENS + s) * 64 + lane] = a;
}

// ---------------------------------------------------------------------------
// Kernel D: conv layers via projected-table gather-accumulate.
// out[b,t,:] = bias + sum_kk ( PV[kk][v] + sum_s PP[kk][s][p] )
// thread = (token, o4): 64 threads (float4) per output token.
// ---------------------------------------------------------------------------
template <int K>
__global__ void __launch_bounds__(256) conv_layer_kernel(
    const int* __restrict__ value,
    const int* __restrict__ position,
    const float* __restrict__ bias,
    float* __restrict__ out,
    int in_start, int out_row_start, int t_per_b)
{
    const float* proj = (K == 4) ? g_proj3 : g_proj4;

    int idx = blockIdx.x * blockDim.x + threadIdx.x;
    int lane  = idx & 63;
    int token = idx >> 6;
    if (token >= BATCH * t_per_b) return;
    int b = token / t_per_b;
    int t = token % t_per_b;

    int sbase = b * S_TOTAL + in_start + t * K;

    float4 acc = reinterpret_cast<const float4*>(bias)[lane];

#pragma unroll
    for (int kk = 0; kk < K; kk++) {
        int s = sbase + kk;
        int v = value[s];
        const int* pp = position + s * 3;
        int q0 = pp[0], q1 = pp[1], q2 = pp[2];

        const float4* P = reinterpret_cast<const float4*>(proj + kk * (NROWS * 256));
        float4 x;
        x = P[v * 64 + lane];
        acc.x += x.x; acc.y += x.y; acc.z += x.z; acc.w += x.w;
        x = P[(4 + q0) * 64 + lane];
        acc.x += x.x; acc.y += x.y; acc.z += x.z; acc.w += x.w;
        x = P[(4 + 64 + q1) * 64 + lane];
        acc.x += x.x; acc.y += x.y; acc.z += x.z; acc.w += x.w;
        x = P[(4 + 128 + q2) * 64 + lane];
        acc.x += x.x; acc.y += x.y; acc.z += x.z; acc.w += x.w;
    }

    int row = b * OUT_TOKENS + out_row_start + t;
    reinterpret_cast<float4*>(out)[row * 64 + lane] = acc;
}

// ---------------------------------------------------------------------------
// Launch.
// Inputs are classified BY ELEMENT COUNT (robust to metadata ordering):
//   value/depth: 8*37448 = 299584 (value first, depth second)
//   position:    898752
//   val_emb_l:   4*256   = 1024    (5 of them, in layer order)
//   pos_emb_l:   3*64*256= 49152   (5, layer order)
//   dep_emb_l:   6*256   = 1536    (3, layer order)
//   conv_w_3:    262144   conv_w_4: 524288
//   conv_b_l:    256      (first seen -> layer 3, second -> layer 4)
// Output: float32 (8, 5704, 256)
// ---------------------------------------------------------------------------
extern "C" void kernel_launch(void* const* d_in, const int* in_sizes, int n_in,
                              void* d_out, int out_size) {
    const int* value = nullptr;
    const int* depth = nullptr;
    const int* position = nullptr;
    const float* val_emb[5] = {};
    const float* pos_emb[5] = {};
    const float* dep_emb[3] = {};
    const float* conv_w3 = nullptr;
    const float* conv_w4 = nullptr;
    const float* conv_b3 = nullptr;
    const float* conv_b4 = nullptr;

    int n_val = 0, n_pos = 0, n_dep = 0, n_cb = 0, n_vd = 0;
    for (int i = 0; i < n_in; i++) {
        int sz = in_sizes[i];
        const void* p = d_in[i];
        switch (sz) {
            case 299584:  // value or depth (both int32, value comes first)
                if (n_vd++ == 0) value = (const int*)p; else depth = (const int*)p;
                break;
            case 898752:  position = (const int*)p; break;
            case 1024:    if (n_val < 5) val_emb[n_val++] = (const float*)p; break;
            case 49152:   if (n_pos < 5) pos_emb[n_pos++] = (const float*)p; break;
            case 1536:    if (n_dep < 3) dep_emb[n_dep++] = (const float*)p; break;
            case 262144:  conv_w3 = (const float*)p; break;
            case 524288:  conv_w4 = (const float*)p; break;
            case 256:
                if (n_cb++ == 0) conv_b3 = (const float*)p; else conv_b4 = (const float*)p;
                break;
            default: break;
        }
    }

    float* out = (float*)d_out;

    // A: transpose weights
    transpose_w_kernel<4><<<(4 * 65536) / 256, 256>>>(conv_w3);
    transpose_w_kernel<8><<<(8 * 65536) / 256, 256>>>(conv_w4);

    // B: project embedding tables through each W_kk
    project_tables_kernel<4><<<dim3(NROWS / RCHUNK, 4), 256>>>(val_emb[3], pos_emb[3]);
    project_tables_kernel<8><<<dim3(NROWS / RCHUNK, 8), 256>>>(val_emb[4], pos_emb[4]);

    // C: small layers 0-2 (584 tokens/batch, direct embedding sum)
    {
        int threads = BATCH * 584 * 64;
        embed_small_kernel<<<(threads + 255) / 256, 256>>>(
            value, depth, position,
            val_emb[0], val_emb[1], val_emb[2],
            pos_emb[0], pos_emb[1], pos_emb[2],
            dep_emb[0], dep_emb[1], dep_emb[2],
            out);
    }

    // D: conv layers via projected-table gathers
    {
        // layer 3: input s in [584, 584+4096), k=4, out rows [584, 1608)
        int threads3 = BATCH * 1024 * 64;
        conv_layer_kernel<4><<<(threads3 + 255) / 256, 256>>>(
            value, position, conv_b3, out,
            /*in_start=*/584, /*out_row_start=*/584, /*t_per_b=*/1024);

        // layer 4: input s in [4680, 37448), k=8, out rows [1608, 5704)
        int threads4 = BATCH * 4096 * 64;
        conv_layer_kernel<8><<<(threads4 + 255) / 256, 256>>>(
            value, position, conv_b4, out,
            /*in_start=*/4680, /*out_row_start=*/1608, /*t_per_b=*/4096);
    }
}

// round 3
// speedup vs baseline: 1.4353x; 1.4353x over previous
#include <cuda_runtime.h>

// Problem constants
#define S_TOTAL    37448       // sum of LAYER_SIZES
#define OUT_TOKENS 5704        // 8 + 64 + 512 + 1024 + 4096
#define BATCH      8
#define NROWS      196         // 4 val rows + 3*64 pos rows
#define PR_ROWS    7           // rows per projection block (28 chunks)

// Scratch (static device globals; no runtime allocation)
__device__ float g_Wt3[4 * 256 * 256];        // [kk][e][o]
__device__ float g_Wt4[8 * 256 * 256];
__device__ float g_proj3[4 * NROWS * 256];    // [kk][row][o]
__device__ float g_proj4[8 * NROWS * 256];

// ---------------------------------------------------------------------------
// Kernel A: tiled transpose  W[o][e][kk] -> Wt[kk][e][o]
// Reads are float4 over kk (coalesced over e-fast threads); writes coalesced
// over o via an smem tile with odd padding (bank-conflict free both phases).
// ---------------------------------------------------------------------------
template <int K>
__global__ void __launch_bounds__(256) transpose_w_tiled(const float* __restrict__ W) {
    constexpr int TO  = (K == 4) ? 64 : 32;   // o-tile
    constexpr int TE  = 32;                   // e-tile
    constexpr int PAD = TO + 1;               // odd stride -> conflict-free
    float* Wt = (K == 4) ? g_Wt3 : g_Wt4;

    __shared__ float sm[K][TE][PAD];

    int o0 = (blockIdx.x % (256 / TO)) * TO;
    int e0 = (blockIdx.x / (256 / TO)) * TE;

    const float4* Wv = reinterpret_cast<const float4*>(W);

    // Load phase: thread-fast dim = e (coalesced float4 reads)
    for (int i = threadIdx.x; i < TO * TE; i += 256) {
        int o_l = i / TE;
        int e_l = i % TE;
        int idx = (o0 + o_l) * 256 + (e0 + e_l);
#pragma unroll
        for (int q = 0; q < K / 4; q++) {
            float4 v = Wv[idx * (K / 4) + q];
            sm[q * 4 + 0][e_l][o_l] = v.x;
            sm[q * 4 + 1][e_l][o_l] = v.y;
            sm[q * 4 + 2][e_l][o_l] = v.z;
            sm[q * 4 + 3][e_l][o_l] = v.w;
        }
    }
    __syncthreads();

    // Store phase: thread-fast dim = o (coalesced writes)
    for (int i = threadIdx.x; i < K * TE * TO; i += 256) {
        int kk  = i / (TE * TO);
        int rem = i % (TE * TO);
        int e_l = rem / TO;
        int o_l = rem % TO;
        Wt[kk * 65536 + (e0 + e_l) * 256 + (o0 + o_l)] = sm[kk][e_l][o_l];
    }
}

// ---------------------------------------------------------------------------
// Kernel B: fused projection for all 12 kk-slices.
// proj[kk][r][o] = sum_e emb_row_r[e] * Wt[kk][e][o]
// grid = (28 row-chunks, 12 slices); block 256 = 64 o-quads x 4 e-quarters.
// Each thread: float4 acc over 7 rows; e-quarter partials combined via smem.
// ---------------------------------------------------------------------------
__global__ void __launch_bounds__(256) project_all_kernel(
    const float* __restrict__ val3, const float* __restrict__ pos3,
    const float* __restrict__ val4, const float* __restrict__ pos4)
{
    int s  = blockIdx.y;            // slice 0..11 (0-3 -> layer3, 4-11 -> layer4)
    int r0 = blockIdx.x * PR_ROWS;  // row chunk base

    const float* Wt; float* proj; const float* ve; const float* pe;
    if (s < 4) { Wt = g_Wt3 + s * 65536;        proj = g_proj3 + s * (NROWS * 256);
                 ve = val3; pe = pos3; }
    else       { int kk = s - 4;
                 Wt = g_Wt4 + kk * 65536;       proj = g_proj4 + kk * (NROWS * 256);
                 ve = val4; pe = pos4; }

    int o4 = threadIdx.x & 63;   // float4 index over o (4 o-values per thread)
    int eh = threadIdx.x >> 6;   // e-quarter 0..3
    int ebase = eh * 64;

    __shared__ float  srow[PR_ROWS][256];
    __shared__ float4 sred[3][PR_ROWS][64];

    // Stage the 7 embedding rows for this chunk
    for (int i = threadIdx.x; i < PR_ROWS * 256; i += 256) {
        int r = i >> 8, c = i & 255;
        int rr = r0 + r;
        srow[r][c] = (rr < 4) ? ve[rr * 256 + c] : pe[(rr - 4) * 256 + c];
    }
    __syncthreads();

    float4 acc[PR_ROWS];
#pragma unroll
    for (int r = 0; r < PR_ROWS; r++) acc[r] = make_float4(0.f, 0.f, 0.f, 0.f);

    const float4* Wv = reinterpret_cast<const float4*>(Wt);
#pragma unroll 8
    for (int e = 0; e < 64; e++) {
        float4 w = Wv[(ebase + e) * 64 + o4];
#pragma unroll
        for (int r = 0; r < PR_ROWS; r++) {
            float x = srow[r][ebase + e];
            acc[r].x += x * w.x; acc[r].y += x * w.y;
            acc[r].z += x * w.z; acc[r].w += x * w.w;
        }
    }

    // Combine the 4 e-quarter partials
    if (eh > 0) {
#pragma unroll
        for (int r = 0; r < PR_ROWS; r++) sred[eh - 1][r][o4] = acc[r];
    }
    __syncthreads();
    if (eh == 0) {
#pragma unroll
        for (int r = 0; r < PR_ROWS; r++) {
            float4 a = acc[r];
            float4 b0 = sred[0][r][o4], b1 = sred[1][r][o4], b2 = sred[2][r][o4];
            a.x += b0.x + b1.x + b2.x;
            a.y += b0.y + b1.y + b2.y;
            a.z += b0.z + b1.z + b2.z;
            a.w += b0.w + b1.w + b2.w;
            reinterpret_cast<float4*>(proj)[(r0 + r) * 64 + o4] = a;
        }
    }
}

// ---------------------------------------------------------------------------
// Kernel C: layers 0-2 (pure embedding sum), 584 tokens per batch row.
// ---------------------------------------------------------------------------
__global__ void __launch_bounds__(256) embed_small_kernel(
    const int* __restrict__ value,
    const int* __restrict__ depth,
    const int* __restrict__ position,
    const float* __restrict__ v0, const float* __restrict__ v1, const float* __restrict__ v2,
    const float* __restrict__ p0, const float* __restrict__ p1, const float* __restrict__ p2,
    const float* __restrict__ d0, const float* __restrict__ d1, const float* __restrict__ d2,
    float* __restrict__ out)
{
    int idx = blockIdx.x * blockDim.x + threadIdx.x;
    int lane  = idx & 63;
    int token = idx >> 6;
    if (token >= BATCH * 584) return;
    int b = token / 584;
    int s = token % 584;

    const float *ve, *pe, *de;
    if (s < 8)       { ve = v0; pe = p0; de = d0; }
    else if (s < 72) { ve = v1; pe = p1; de = d1; }
    else             { ve = v2; pe = p2; de = d2; }

    int base = b * S_TOTAL + s;
    int v = value[base];
    int d = depth[base];
    const int* pp = position + base * 3;
    int q0 = pp[0], q1 = pp[1], q2 = pp[2];

    const float4* V  = reinterpret_cast<const float4*>(ve) + v * 64 + lane;
    const float4* P0 = reinterpret_cast<const float4*>(pe) + (q0)       * 64 + lane;
    const float4* P1 = reinterpret_cast<const float4*>(pe) + (64 + q1)  * 64 + lane;
    const float4* P2 = reinterpret_cast<const float4*>(pe) + (128 + q2) * 64 + lane;
    const float4* D  = reinterpret_cast<const float4*>(de) + d * 64 + lane;

    float4 a = *V, x;
    x = *P0; a.x += x.x; a.y += x.y; a.z += x.z; a.w += x.w;
    x = *P1; a.x += x.x; a.y += x.y; a.z += x.z; a.w += x.w;
    x = *P2; a.x += x.x; a.y += x.y; a.z += x.z; a.w += x.w;
    x = *D;  a.x += x.x; a.y += x.y; a.z += x.z; a.w += x.w;

    reinterpret_cast<float4*>(out)[(b * OUT_TOKENS + s) * 64 + lane] = a;
}

// ---------------------------------------------------------------------------
// Kernel D: conv layers via projected-table gather-accumulate.
// ---------------------------------------------------------------------------
template <int K>
__global__ void __launch_bounds__(256) conv_layer_kernel(
    const int* __restrict__ value,
    const int* __restrict__ position,
    const float* __restrict__ bias,
    float* __restrict__ out,
    int in_start, int out_row_start, int t_per_b)
{
    const float* proj = (K == 4) ? g_proj3 : g_proj4;

    int idx = blockIdx.x * blockDim.x + threadIdx.x;
    int lane  = idx & 63;
    int token = idx >> 6;
    if (token >= BATCH * t_per_b) return;
    int b = token / t_per_b;
    int t = token % t_per_b;

    int sbase = b * S_TOTAL + in_start + t * K;

    float4 acc = reinterpret_cast<const float4*>(bias)[lane];

#pragma unroll
    for (int kk = 0; kk < K; kk++) {
        int s = sbase + kk;
        int v = value[s];
        const int* pp = position + s * 3;
        int q0 = pp[0], q1 = pp[1], q2 = pp[2];

        const float4* P = reinterpret_cast<const float4*>(proj + kk * (NROWS * 256));
        float4 x;
        x = P[v * 64 + lane];
        acc.x += x.x; acc.y += x.y; acc.z += x.z; acc.w += x.w;
        x = P[(4 + q0) * 64 + lane];
        acc.x += x.x; acc.y += x.y; acc.z += x.z; acc.w += x.w;
        x = P[(4 + 64 + q1) * 64 + lane];
        acc.x += x.x; acc.y += x.y; acc.z += x.z; acc.w += x.w;
        x = P[(4 + 128 + q2) * 64 + lane];
        acc.x += x.x; acc.y += x.y; acc.z += x.z; acc.w += x.w;
    }

    int row = b * OUT_TOKENS + out_row_start + t;
    reinterpret_cast<float4*>(out)[row * 64 + lane] = acc;
}

// ---------------------------------------------------------------------------
// Launch. Inputs classified BY ELEMENT COUNT (robust to metadata ordering).
// ---------------------------------------------------------------------------
extern "C" void kernel_launch(void* const* d_in, const int* in_sizes, int n_in,
                              void* d_out, int out_size) {
    const int* value = nullptr;
    const int* depth = nullptr;
    const int* position = nullptr;
    const float* val_emb[5] = {};
    const float* pos_emb[5] = {};
    const float* dep_emb[3] = {};
    const float* conv_w3 = nullptr;
    const float* conv_w4 = nullptr;
    const float* conv_b3 = nullptr;
    const float* conv_b4 = nullptr;

    int n_val = 0, n_pos = 0, n_dep = 0, n_cb = 0, n_vd = 0;
    for (int i = 0; i < n_in; i++) {
        int sz = in_sizes[i];
        const void* p = d_in[i];
        switch (sz) {
            case 299584:
                if (n_vd++ == 0) value = (const int*)p; else depth = (const int*)p;
                break;
            case 898752:  position = (const int*)p; break;
            case 1024:    if (n_val < 5) val_emb[n_val++] = (const float*)p; break;
            case 49152:   if (n_pos < 5) pos_emb[n_pos++] = (const float*)p; break;
            case 1536:    if (n_dep < 3) dep_emb[n_dep++] = (const float*)p; break;
            case 262144:  conv_w3 = (const float*)p; break;
            case 524288:  conv_w4 = (const float*)p; break;
            case 256:
                if (n_cb++ == 0) conv_b3 = (const float*)p; else conv_b4 = (const float*)p;
                break;
            default: break;
        }
    }

    float* out = (float*)d_out;

    // A: tiled transposes (coalesced both sides)
    transpose_w_tiled<4><<<(256 / 64) * (256 / 32), 256>>>(conv_w3);
    transpose_w_tiled<8><<<(256 / 32) * (256 / 32), 256>>>(conv_w4);

    // B: fused projection, all 12 kk-slices in one launch
    project_all_kernel<<<dim3(NROWS / PR_ROWS, 12), 256>>>(
        val_emb[3], pos_emb[3], val_emb[4], pos_emb[4]);

    // C: small layers 0-2
    {
        int threads = BATCH * 584 * 64;
        embed_small_kernel<<<(threads + 255) / 256, 256>>>(
            value, depth, position,
            val_emb[0], val_emb[1], val_emb[2],
            pos_emb[0], pos_emb[1], pos_emb[2],
            dep_emb[0], dep_emb[1], dep_emb[2],
            out);
    }

    // D: conv layers via projected-table gathers
    {
        int threads3 = BATCH * 1024 * 64;
        conv_layer_kernel<4><<<(threads3 + 255) / 256, 256>>>(
            value, position, conv_b3, out,
            /*in_start=*/584, /*out_row_start=*/584, /*t_per_b=*/1024);

        int threads4 = BATCH * 4096 * 64;
        conv_layer_kernel<8><<<(threads4 + 255) / 256, 256>>>(
            value, position, conv_b4, out,
            /*in_start=*/4680, /*out_row_start=*/1608, /*t_per_b=*/4096);
    }
}